// round 9
// baseline (speedup 1.0000x reference)
#include <cuda_runtime.h>
#include <cuda_bf16.h>
#include <cstdint>

// RepeatEncoder: LIF spiking neuron over T=32 repeated presentations of the
// same frame. Input [B=64, C=64, L=512] fp32 -> output [B, T=32, L, C] fp32.
//
// Per (b,l,c): x = in[b,c,l]; v=0; for t in 0..31:
//   v += (x - v)*0.5;  s = (v >= 1);  v = s ? 0 : v;  out[b,t,l,c] = s
//
// DRAM-write-stream bound (256 MB out / replay). R8 change: LT=64 so the
// grid is 512 CTAs -> one full wave at 4 CTAs/SM (was 1024 CTAs = 2 waves
// with tail). Each thread now owns 2 l-rows x 4 channels. Streaming .cs
// stores (R6) and coalesced smem input staging (R5) retained.

namespace {
constexpr int B  = 64;
constexpr int C  = 64;
constexpr int L  = 512;
constexpr int T  = 32;
constexpr int LT = 64;                 // l-tile per block
constexpr int THREADS = 512;
constexpr int PITCH = LT + 1;          // smem pitch (65 floats)
}

__global__ void __launch_bounds__(THREADS)
lif_repeat_encoder_kernel(const float* __restrict__ in, float* __restrict__ out) {
    __shared__ float tile[C * PITCH];  // tile[c][ll], pitch 65 (~16.25 KB)

    const int tid = threadIdx.x;
    const int bid = blockIdx.x;        // 0 .. B*(L/LT)-1 = 511
    const int b   = bid >> 3;          // bid / (L/LT=8)
    const int l0  = (bid & 7) << 6;    // (bid % 8) * 64

    // ---- Coalesced load: input [B, C, L]; block needs [b, 0:64, l0:l0+64].
    // Each warp loads 32 consecutive floats (128B). 8 rows per thread.
    {
        const int ll = tid & 63;       // l within tile
        const int cr = tid >> 6;       // 0..7
        const float* src = in + ((size_t)b * C) * L + l0 + ll;
        #pragma unroll
        for (int i = 0; i < 8; ++i) {
            const int c = cr + i * 8;
            tile[c * PITCH + ll] = src[(size_t)c * L];
        }
    }
    __syncthreads();

    // ---- Compute + store: thread owns (llb, llb+32) x 4 consecutive channels.
    const int c4  = tid & 15;          // channel group 0..15
    const int llb = tid >> 4;          // l within tile 0..31 (second row +32)
    const int c   = c4 * 4;

    const float xa0 = tile[(c + 0) * PITCH + llb];
    const float xa1 = tile[(c + 1) * PITCH + llb];
    const float xa2 = tile[(c + 2) * PITCH + llb];
    const float xa3 = tile[(c + 3) * PITCH + llb];
    const float xb0 = tile[(c + 0) * PITCH + llb + 32];
    const float xb1 = tile[(c + 1) * PITCH + llb + 32];
    const float xb2 = tile[(c + 2) * PITCH + llb + 32];
    const float xb3 = tile[(c + 3) * PITCH + llb + 32];

    float va0 = 0.f, va1 = 0.f, va2 = 0.f, va3 = 0.f;
    float vb0 = 0.f, vb1 = 0.f, vb2 = 0.f, vb3 = 0.f;

    // Output [B, T, L, C]: row A at l = l0+llb, row B at l+32.
    float4* outA = reinterpret_cast<float4*>(
        out + ((size_t)b * T * L + l0 + llb) * C + c);
    float4* outB = outA + (size_t)32 * C / 4;      // +32 l-rows
    constexpr size_t strideT4 = (size_t)L * C / 4; // float4 per timestep

    #pragma unroll
    for (int t = 0; t < T; ++t) {
        // v = v + (x - v)/tau, tau = 2 (mul by 0.5 is exact)
        va0 += (xa0 - va0) * 0.5f;  va1 += (xa1 - va1) * 0.5f;
        va2 += (xa2 - va2) * 0.5f;  va3 += (xa3 - va3) * 0.5f;
        vb0 += (xb0 - vb0) * 0.5f;  vb1 += (xb1 - vb1) * 0.5f;
        vb2 += (xb2 - vb2) * 0.5f;  vb3 += (xb3 - vb3) * 0.5f;

        const float sa0 = (va0 >= 1.0f) ? 1.0f : 0.0f;
        const float sa1 = (va1 >= 1.0f) ? 1.0f : 0.0f;
        const float sa2 = (va2 >= 1.0f) ? 1.0f : 0.0f;
        const float sa3 = (va3 >= 1.0f) ? 1.0f : 0.0f;
        const float sb0 = (vb0 >= 1.0f) ? 1.0f : 0.0f;
        const float sb1 = (vb1 >= 1.0f) ? 1.0f : 0.0f;
        const float sb2 = (vb2 >= 1.0f) ? 1.0f : 0.0f;
        const float sb3 = (vb3 >= 1.0f) ? 1.0f : 0.0f;

        va0 = (sa0 != 0.0f) ? 0.0f : va0;  va1 = (sa1 != 0.0f) ? 0.0f : va1;
        va2 = (sa2 != 0.0f) ? 0.0f : va2;  va3 = (sa3 != 0.0f) ? 0.0f : va3;
        vb0 = (sb0 != 0.0f) ? 0.0f : vb0;  vb1 = (sb1 != 0.0f) ? 0.0f : vb1;
        vb2 = (sb2 != 0.0f) ? 0.0f : vb2;  vb3 = (sb3 != 0.0f) ? 0.0f : vb3;

        // Streaming stores: evict-first, never re-read on-chip.
        __stcs(outA + (size_t)t * strideT4, make_float4(sa0, sa1, sa2, sa3));
        __stcs(outB + (size_t)t * strideT4, make_float4(sb0, sb1, sb2, sb3));
    }
}

extern "C" void kernel_launch(void* const* d_in, const int* in_sizes, int n_in,
                              void* d_out, int out_size) {
    (void)in_sizes; (void)n_in; (void)out_size;
    const float* in = (const float*)d_in[0];
    float* out = (float*)d_out;

    const int blocks = B * (L / LT);   // 512 -> single wave at 4 CTAs/SM
    lif_repeat_encoder_kernel<<<blocks, THREADS>>>(in, out);
}

// round 10
// speedup vs baseline: 1.1412x; 1.1412x over previous
#include <cuda_runtime.h>
#include <cuda_bf16.h>
#include <cstdint>

// RepeatEncoder: LIF spiking neuron over T=32 repeated presentations of the
// same frame. Input [B=64, C=64, L=512] fp32 -> output [B, T=32, L, C] fp32.
//
// Per (b,l,c): x = in[b,c,l]; v=0; for t in 0..31:
//   v += (x - v)*0.5;  s = (v >= 1);  v = s ? 0 : v;  out[b,t,l,c] = s
//
// DRAM-write-stream bound (256 MB out / replay). R9: R8's coarse tiles
// (LT=64) regressed via per-SM CTA-count imbalance -> go FINER instead:
// 256-thread CTAs, LT=16, grid=2048, occ 8 CTAs/SM. Halves the tail
// quantization of R6 while keeping coalesced smem staging (R5) and
// evict-first .cs streaming stores (R6).

namespace {
constexpr int B  = 64;
constexpr int C  = 64;
constexpr int L  = 512;
constexpr int T  = 32;
constexpr int LT = 16;                 // l-tile per block
constexpr int THREADS = 256;           // = LT * (C/4)
constexpr int PITCH = LT + 1;          // smem pitch (17 floats)
}

__global__ void __launch_bounds__(THREADS)
lif_repeat_encoder_kernel(const float* __restrict__ in, float* __restrict__ out) {
    __shared__ float tile[C * PITCH];  // tile[c][ll], ~4.25 KB

    const int tid = threadIdx.x;
    const int bid = blockIdx.x;        // 0 .. B*(L/LT)-1 = 2047
    const int b   = bid >> 5;          // bid / (L/LT=32)
    const int l0  = (bid & 31) << 4;   // (bid % 32) * 16

    // ---- Coalesced load: input [B, C, L]; block needs [b, 0:64, l0:l0+16].
    // ll = tid&15 -> 16 consecutive floats (64B run) per half-warp; each warp
    // touches 2 c-rows x 64B. 4 iterations x 256 threads = 1024 floats.
    {
        const int ll = tid & 15;       // l within tile
        const int cr = tid >> 4;       // 0..15
        const float* src = in + ((size_t)b * C) * L + l0 + ll;
        #pragma unroll
        for (int i = 0; i < 4; ++i) {
            const int c = cr + i * 16;
            tile[c * PITCH + ll] = src[(size_t)c * L];
        }
    }
    __syncthreads();

    // ---- Compute + store: thread owns (ll, 4 consecutive channels).
    const int c4 = tid & 15;           // channel group 0..15
    const int ll = tid >> 4;           // l within tile 0..15
    const int c  = c4 * 4;
    const int l  = l0 + ll;

    const float x0 = tile[(c + 0) * PITCH + ll];
    const float x1 = tile[(c + 1) * PITCH + ll];
    const float x2 = tile[(c + 2) * PITCH + ll];
    const float x3 = tile[(c + 3) * PITCH + ll];

    float v0 = 0.f, v1 = 0.f, v2 = 0.f, v3 = 0.f;

    // Output [B, T, L, C]: base at t=0, stride L*C floats per timestep.
    // Warp stores 512B contiguous (lanes 0-15 one l-row, 16-31 the next).
    float4* outp = reinterpret_cast<float4*>(
        out + ((size_t)b * T * L + l) * C + c);
    constexpr size_t strideT4 = (size_t)L * C / 4;

    #pragma unroll
    for (int t = 0; t < T; ++t) {
        // v = v + (x - v)/tau, tau = 2 (mul by 0.5 is exact)
        v0 += (x0 - v0) * 0.5f;
        v1 += (x1 - v1) * 0.5f;
        v2 += (x2 - v2) * 0.5f;
        v3 += (x3 - v3) * 0.5f;

        const float s0 = (v0 >= 1.0f) ? 1.0f : 0.0f;
        const float s1 = (v1 >= 1.0f) ? 1.0f : 0.0f;
        const float s2 = (v2 >= 1.0f) ? 1.0f : 0.0f;
        const float s3 = (v3 >= 1.0f) ? 1.0f : 0.0f;

        v0 = (s0 != 0.0f) ? 0.0f : v0;
        v1 = (s1 != 0.0f) ? 0.0f : v1;
        v2 = (s2 != 0.0f) ? 0.0f : v2;
        v3 = (s3 != 0.0f) ? 0.0f : v3;

        // Streaming store: evict-first, never re-read on-chip.
        __stcs(outp + (size_t)t * strideT4, make_float4(s0, s1, s2, s3));
    }
}

extern "C" void kernel_launch(void* const* d_in, const int* in_sizes, int n_in,
                              void* d_out, int out_size) {
    (void)in_sizes; (void)n_in; (void)out_size;
    const float* in = (const float*)d_in[0];
    float* out = (float*)d_out;

    const int blocks = B * (L / LT);   // 2048
    lif_repeat_encoder_kernel<<<blocks, THREADS>>>(in, out);
}